// round 7
// baseline (speedup 1.0000x reference)
#include <cuda_runtime.h>
#include <cstdint>

#define PPIX 3136
#define CH 256
#define DIM 32
#define KER 7
#define K2 49
#define TILE 14
#define HALO 20
#define HALOSZ 400
#define ROWP 36

// scratch (allocation-free rule: device globals)
__device__ __align__(16) float g_Qp[2 * PPIX * CH];
__device__ __align__(16) float g_Kp[2 * PPIX * CH];
__device__ __align__(16) float g_Vp[2 * PPIX * CH];
__device__ __align__(16) float g_O [2 * PPIX * CH];
__device__ __align__(16) float g_Wt[4 * CH * CH];     // tf32-rounded Wq,Wk,Wv,Wout
__device__ __align__(16) float g_bck[CH];
__device__ __align__(16) float g_bcv[CH];

// ---------------------------------------------------------------------------
// helpers
// ---------------------------------------------------------------------------
__device__ __forceinline__ uint32_t f2tf(float x) {
    uint32_t r;
    asm("cvt.rna.tf32.f32 %0, %1;" : "=r"(r) : "f"(x));
    return r;
}
__device__ __forceinline__ float f2tf_f(float x) { return __uint_as_float(f2tf(x)); }
__device__ __forceinline__ void mma_tf32(float c[4], const uint32_t a[4], const uint32_t b[2]) {
    asm volatile(
        "mma.sync.aligned.m16n8k8.row.col.f32.tf32.tf32.f32 "
        "{%0,%1,%2,%3}, {%4,%5,%6,%7}, {%8,%9}, {%0,%1,%2,%3};"
        : "+f"(c[0]), "+f"(c[1]), "+f"(c[2]), "+f"(c[3])
        : "r"(a[0]), "r"(a[1]), "r"(a[2]), "r"(a[3]), "r"(b[0]), "r"(b[1]));
}
__device__ __forceinline__ void cp16(float* smem_dst, const float* gmem_src) {
    uint32_t s = (uint32_t)__cvta_generic_to_shared(smem_dst);
    asm volatile("cp.async.cg.shared.global [%0], [%1], 16;" :: "r"(s), "l"(gmem_src));
}
#define CP_COMMIT()  asm volatile("cp.async.commit_group;")
#define CP_WAIT1()   asm volatile("cp.async.wait_group 1;")

#define NSTG 3
#define PROJ_STG 9216    // A[32][72] + 3x B[64][36]  (floats)
#define OUT_STG  6912    // A0[64][36] + A1[64][36] + B[64][36]

// ---------------------------------------------------------------------------
// tf32-round all weights into g_Wt:  [0..3*CH*CH) = in_proj, then out_proj
// ---------------------------------------------------------------------------
__global__ void w_tf32_kernel(const float* __restrict__ ipw, const float* __restrict__ opw) {
    int i = blockIdx.x * 128 + threadIdx.x;            // float4 index, 65536 total
    const int IPW4 = 3 * CH * CH / 4;                   // 49152
    float4 v = (i < IPW4) ? reinterpret_cast<const float4*>(ipw)[i]
                          : reinterpret_cast<const float4*>(opw)[i - IPW4];
    v.x = f2tf_f(v.x); v.y = f2tf_f(v.y); v.z = f2tf_f(v.z); v.w = f2tf_f(v.w);
    reinterpret_cast<float4*>(g_Wt)[i] = v;
}

// ---------------------------------------------------------------------------
// bconst[c'] = pos * sum_c W[c'][c] + b[c']   (K and V blocks of in_proj)
// ---------------------------------------------------------------------------
__global__ void bconst_kernel(const float* __restrict__ W, const float* __restrict__ b,
                              const float* __restrict__ pos) {
    int c = blockIdx.x * 8 + (threadIdx.x >> 5);
    int lane = threadIdx.x & 31;
    float p = pos[0];
    const float4* wk = reinterpret_cast<const float4*>(W + (size_t)(CH + c) * CH);
    const float4* wv = reinterpret_cast<const float4*>(W + (size_t)(2 * CH + c) * CH);
    float4 a0 = wk[lane * 2], a1 = wk[lane * 2 + 1];
    float4 v0 = wv[lane * 2], v1 = wv[lane * 2 + 1];
    float sk = a0.x + a0.y + a0.z + a0.w + a1.x + a1.y + a1.z + a1.w;
    float sv = v0.x + v0.y + v0.z + v0.w + v1.x + v1.y + v1.z + v1.w;
    #pragma unroll
    for (int o = 16; o > 0; o >>= 1) {
        sk += __shfl_xor_sync(0xffffffffu, sk, o);
        sv += __shfl_xor_sync(0xffffffffu, sv, o);
    }
    if (lane == 0) {
        g_bck[c] = p * sk + b[CH + c];
        g_bcv[c] = p * sv + b[2 * CH + c];
    }
}

// ---------------------------------------------------------------------------
// Fused Q/K/V projection (tf32, BM=64 BN=64 BK=32, cp.async 3-stage):
//   For one n and one (m0,c0) tile, computes Q,K,V outputs simultaneously —
//   A (In) tile loaded ONCE, 3 weight tiles, 3 accumulators, 24 MMAs/kstep.
// In channel-major (C,P) -> A smem k-major [32][72]; W tf32 -> B n-major [64][36].
// blockIdx.z = n
// ---------------------------------------------------------------------------
__global__ void __launch_bounds__(128, 2)
proj_gemm(const float* __restrict__ queries, const float* __restrict__ key,
          const float* __restrict__ bvec) {
    int n = blockIdx.z;
    const float* InQ = queries + (size_t)n * CH * PPIX;
    const float* InK = key     + (size_t)n * CH * PPIX;

    extern __shared__ float smf[];     // [NSTG][PROJ_STG]

    int tid = threadIdx.x;
    int m0 = blockIdx.x * 64;
    int c0 = blockIdx.y * 64;
    int w = tid >> 5, lane = tid & 31;
    int r = lane >> 2, tig = lane & 3;
    int wm = (w & 1) * 32;
    int wn = (w >> 1) * 32;

    float acc[3][2][4][4] = {};

    auto issue_tile = [&](int t, int stg) {
        float* As = smf + stg * PROJ_STG;
        int kt = t * 32;
        #pragma unroll
        for (int i = 0; i < 4; i++) {
            int id = tid + 128 * i;
            int row = id >> 4;                 // 0..31
            int c4 = (id & 15) * 4;            // 0..60
            // proj 0 (Q) reads queries; projs 1,2 (K,V) read key — same A for K,V!
            // A layout: first half rows from queries? No: A is per-source.
            // We store TWO A tiles? K and V share In=key; Q uses queries.
            cp16(As + row * 72 + c4, InQ + (size_t)(kt + row) * PPIX + m0 + c4);
        }
        // second A tile (key) lives right after the 3 B tiles
        float* Ak = As + 2304 + 3 * 2304 - 2304;   // placeholder (overwritten below)
        (void)Ak;
        #pragma unroll
        for (int pr = 0; pr < 3; pr++) {
            const float* W = g_Wt + (size_t)pr * CH * CH;
            float* Bs = As + 2304 + pr * 2304;
            #pragma unroll
            for (int i = 0; i < 4; i++) {
                int id = tid + 128 * i;
                int row = id >> 3;             // 0..63
                int k4 = (id & 7) * 4;         // 0..28
                cp16(Bs + row * 36 + k4, W + (size_t)(c0 + row) * CH + kt + k4);
            }
        }
        CP_COMMIT();
    };
    // NOTE on A tiles: Q projects `queries`, K/V project `key`. We need both
    // A tiles in smem. Trick: K,V share one tile. Layout per stage:
    //   [0,2304)      A_q (queries)
    //   [2304,2304*4) B_q, B_k, B_v
    // and A_k is loaded into ... we need a 5th tile. Simplest: extend the
    // stage by one more 2304 block for A_k (done via PROJ_STG sizing? kept
    // at 9216 = 4 tiles). Instead we exploit: Q-GEMM uses A_q with B_q;
    // K/V GEMMs use A_k with B_k,B_v. So stage = A_q + A_k + B_q + B_k + B_v
    // would be 5 tiles. To stay at 4 tiles, we instead note K and V share
    // A_k, and run the Q accumulation from A_q. We therefore DO need 5 tiles.
    // -> see issue_tile2 below which is the real loader (5 tiles/stage).

    (void)issue_tile;

    // real stage layout (5 tiles): A_q | A_k | B_q | B_k | B_v
    auto issue5 = [&](int t, int stg) {
        float* base = smf + stg * (5 * 2304);
        int kt = t * 32;
        #pragma unroll
        for (int i = 0; i < 4; i++) {
            int id = tid + 128 * i;
            int row = id >> 4;
            int c4 = (id & 15) * 4;
            cp16(base + row * 72 + c4,        InQ + (size_t)(kt + row) * PPIX + m0 + c4);
            cp16(base + 2304 + row * 72 + c4, InK + (size_t)(kt + row) * PPIX + m0 + c4);
        }
        #pragma unroll
        for (int pr = 0; pr < 3; pr++) {
            const float* W = g_Wt + (size_t)pr * CH * CH;
            float* Bs = base + 2 * 2304 + pr * 2304;
            #pragma unroll
            for (int i = 0; i < 4; i++) {
                int id = tid + 128 * i;
                int row = id >> 3;
                int k4 = (id & 7) * 4;
                cp16(Bs + row * 36 + k4, W + (size_t)(c0 + row) * CH + kt + k4);
            }
        }
        CP_COMMIT();
    };

    issue5(0, 0);
    issue5(1, 1);

    for (int it = 0; it < 8; it++) {
        CP_WAIT1();
        __syncthreads();
        if (it + 2 < 8) issue5(it + 2, (it + 2) % NSTG);

        const float* base = smf + (it % NSTG) * (5 * 2304);
        #pragma unroll
        for (int ks = 0; ks < 4; ks++) {
            int k0 = ks * 8;
            uint32_t aq[2][4], ak[2][4];
            #pragma unroll
            for (int mt = 0; mt < 2; mt++) {
                int m = wm + mt * 16 + r;
                aq[mt][0] = f2tf(base[(k0 + tig) * 72 + m]);
                aq[mt][1] = f2tf(base[(k0 + tig) * 72 + m + 8]);
                aq[mt][2] = f2tf(base[(k0 + tig + 4) * 72 + m]);
                aq[mt][3] = f2tf(base[(k0 + tig + 4) * 72 + m + 8]);
                ak[mt][0] = f2tf(base[2304 + (k0 + tig) * 72 + m]);
                ak[mt][1] = f2tf(base[2304 + (k0 + tig) * 72 + m + 8]);
                ak[mt][2] = f2tf(base[2304 + (k0 + tig + 4) * 72 + m]);
                ak[mt][3] = f2tf(base[2304 + (k0 + tig + 4) * 72 + m + 8]);
            }
            #pragma unroll
            for (int pr = 0; pr < 3; pr++) {
                const float* Bb = base + 2 * 2304 + pr * 2304;
                uint32_t b[4][2];
                #pragma unroll
                for (int nt = 0; nt < 4; nt++) {
                    int nn = wn + nt * 8 + r;
                    b[nt][0] = __float_as_uint(Bb[nn * 36 + k0 + tig]);
                    b[nt][1] = __float_as_uint(Bb[nn * 36 + k0 + tig + 4]);
                }
                #pragma unroll
                for (int mt = 0; mt < 2; mt++)
                    #pragma unroll
                    for (int nt = 0; nt < 4; nt++)
                        mma_tf32(acc[pr][mt][nt], (pr == 0) ? aq[mt] : ak[mt], b[nt]);
            }
        }
    }

    float* Outs[3] = { g_Qp + (size_t)n * PPIX * CH,
                       g_Kp + (size_t)n * PPIX * CH,
                       g_Vp + (size_t)n * PPIX * CH };
    #pragma unroll
    for (int pr = 0; pr < 3; pr++) {
        float* Out = Outs[pr];
        #pragma unroll
        for (int mt = 0; mt < 2; mt++) {
            int row0 = m0 + wm + mt * 16 + r;
            #pragma unroll
            for (int nt = 0; nt < 4; nt++) {
                int cc = c0 + wn + nt * 8 + 2 * tig;
                float b0 = (pr == 0) ? bvec[cc] : 0.f;
                float b1 = (pr == 0) ? bvec[cc + 1] : 0.f;
                *reinterpret_cast<float2*>(Out + (size_t)row0 * CH + cc) =
                    make_float2(acc[pr][mt][nt][0] + b0, acc[pr][mt][nt][1] + b1);
                *reinterpret_cast<float2*>(Out + (size_t)(row0 + 8) * CH + cc) =
                    make_float2(acc[pr][mt][nt][2] + b0, acc[pr][mt][nt][3] + b1);
            }
        }
    }
}

// ---------------------------------------------------------------------------
// Local attention: 1 pixel/thread, 256 threads, phase-split smem, 2 blocks/SM.
// Output stored tf32-rounded (outproj then needs no cvt; numerically identical).
// ---------------------------------------------------------------------------
__global__ void __launch_bounds__(256, 2) attn_kernel() {
    extern __shared__ float smf[];     // HALOSZ * ROWP floats

    int tx0 = blockIdx.x * TILE;
    int ty0 = blockIdx.y * TILE;
    int h = blockIdx.z & 7;
    int n = blockIdx.z >> 3;
    int tid = threadIdx.x;
    int cbase = h * DIM;

    const float* Kp = g_Kp + (size_t)n * PPIX * CH;
    const float* Vp = g_Vp + (size_t)n * PPIX * CH;

    int ly = tid / TILE, lx = tid % TILE;
    bool active = tid < TILE * TILE;
    int p = (ty0 + ly) * 56 + (tx0 + lx);

    float4 q4[8];
    if (active) {
        const float* qptr = g_Qp + (size_t)n * PPIX * CH + (size_t)p * CH + cbase;
        #pragma unroll
        for (int i = 0; i < 8; i++)
            q4[i] = *reinterpret_cast<const float4*>(qptr + i * 4);
    }

    // ---- phase 1: K halo fill ----
    for (int idx = tid; idx < HALOSZ * 8; idx += 256) {
        int hp = idx >> 3;
        int c4 = (idx & 7) * 4;
        int gy = ty0 - 3 + hp / HALO;
        int gx = tx0 - 3 + hp % HALO;
        float4 kv = *reinterpret_cast<const float4*>(g_bck + cbase + c4);
        if (gy >= 0 && gy < 56 && gx >= 0 && gx < 56) {
            float4 k4 = *reinterpret_cast<const float4*>(Kp + (size_t)(gy * 56 + gx) * CH + cbase + c4);
            kv.x += k4.x; kv.y += k4.y; kv.z += k4.z; kv.w += k4.w;
        }
        *reinterpret_cast<float4*>(smf + hp * ROWP + c4) = kv;
    }
    __syncthreads();

    float sc[K2];
    if (active) {
        const float scale = 0.17677669529663687f;   // 1/sqrt(32)
        #pragma unroll
        for (int ti = 0; ti < KER; ti++) {
            #pragma unroll
            for (int tj = 0; tj < KER; tj++) {
                const float4* kr = reinterpret_cast<const float4*>(
                    smf + ((ly + ti) * HALO + (lx + tj)) * ROWP);
                float s = 0.f;
                #pragma unroll
                for (int c = 0; c < 8; c++) {
                    float4 k4 = kr[c];
                    s += q4[c].x * k4.x + q4[c].y * k4.y + q4[c].z * k4.z + q4[c].w * k4.w;
                }
                sc[ti * KER + tj] = s * scale;
            }
        }
        float mx = sc[0];
        #pragma unroll
        for (int t = 1; t < K2; t++) mx = fmaxf(mx, sc[t]);
        float sum = 0.f;
        #pragma unroll
        for (int t = 0; t < K2; t++) { sc[t] = __expf(sc[t] - mx); sum += sc[t]; }
        float inv = 1.f / sum;
        #pragma unroll
        for (int t = 0; t < K2; t++) sc[t] *= inv;
    }
    __syncthreads();

    // ---- phase 2: V halo fill (same buffer) ----
    for (int idx = tid; idx < HALOSZ * 8; idx += 256) {
        int hp = idx >> 3;
        int c4 = (idx & 7) * 4;
        int gy = ty0 - 3 + hp / HALO;
        int gx = tx0 - 3 + hp % HALO;
        float4 vv = *reinterpret_cast<const float4*>(g_bcv + cbase + c4);
        if (gy >= 0 && gy < 56 && gx >= 0 && gx < 56) {
            float4 v4 = *reinterpret_cast<const float4*>(Vp + (size_t)(gy * 56 + gx) * CH + cbase + c4);
            vv.x += v4.x; vv.y += v4.y; vv.z += v4.z; vv.w += v4.w;
        }
        *reinterpret_cast<float4*>(smf + hp * ROWP + c4) = vv;
    }
    __syncthreads();

    if (active) {
        float4 o4[8];
        #pragma unroll
        for (int c = 0; c < 8; c++) o4[c] = make_float4(0.f, 0.f, 0.f, 0.f);
        #pragma unroll
        for (int ti = 0; ti < KER; ti++) {
            #pragma unroll
            for (int tj = 0; tj < KER; tj++) {
                const float4* vr = reinterpret_cast<const float4*>(
                    smf + ((ly + ti) * HALO + (lx + tj)) * ROWP);
                float wgt = sc[ti * KER + tj];
                #pragma unroll
                for (int c = 0; c < 8; c++) {
                    float4 v4 = vr[c];
                    o4[c].x += wgt * v4.x; o4[c].y += wgt * v4.y;
                    o4[c].z += wgt * v4.z; o4[c].w += wgt * v4.w;
                }
            }
        }
        float* optr = g_O + (size_t)n * PPIX * CH + (size_t)p * CH + cbase;
        #pragma unroll
        for (int i = 0; i < 8; i++) {
            float4 t = o4[i];
            t.x = f2tf_f(t.x); t.y = f2tf_f(t.y); t.z = f2tf_f(t.z); t.w = f2tf_f(t.w);
            *reinterpret_cast<float4*>(optr + i * 4) = t;
        }
    }
}

// ---------------------------------------------------------------------------
// Out projection, both batches fused (tf32, BM=64 BN=64 BK=32, 3-stage):
//   out[n][c'][p] = sum_c O[n][p][c] * Wout[c'][c] + bout[c']
// Stage = A0[64][36] + A1[64][36] + B[64][36].  No cvts (inputs tf32-rounded).
// ---------------------------------------------------------------------------
__global__ void __launch_bounds__(128, 2)
outproj_gemm(const float* __restrict__ bout, float* __restrict__ out) {
    extern __shared__ float smf[];     // [NSTG][OUT_STG]
    const float* Wout = g_Wt + 3 * CH * CH;

    int tid = threadIdx.x;
    int m0 = blockIdx.x * 64;
    int c0 = blockIdx.y * 64;
    int w = tid >> 5, lane = tid & 31;
    int r = lane >> 2, tig = lane & 3;
    int wm = (w & 1) * 32;
    int wn = (w >> 1) * 32;

    float acc[2][2][4][4] = {};

    auto issue_tile = [&](int t, int stg) {
        float* base = smf + stg * OUT_STG;
        int kt = t * 32;
        #pragma unroll
        for (int i = 0; i < 4; i++) {
            int id = tid + 128 * i;
            int row = id >> 3;                 // 0..63
            int k4 = (id & 7) * 4;
            cp16(base + row * 36 + k4,
                 g_O + (size_t)(m0 + row) * CH + kt + k4);
            cp16(base + 2304 + row * 36 + k4,
                 g_O + (size_t)PPIX * CH + (size_t)(m0 + row) * CH + kt + k4);
            cp16(base + 4608 + row * 36 + k4,
                 Wout + (size_t)(c0 + row) * CH + kt + k4);
        }
        CP_COMMIT();
    };

    issue_tile(0, 0);
    issue_tile(1, 1);

    for (int it = 0; it < 8; it++) {
        CP_WAIT1();
        __syncthreads();
        if (it + 2 < 8) issue_tile(it + 2, (it + 2) % NSTG);

        const float* base = smf + (it % NSTG) * OUT_STG;
        #pragma unroll
        for (int ks = 0; ks < 4; ks++) {
            int k0 = ks * 8;
            uint32_t a[2][2][4], b[4][2];
            #pragma unroll
            for (int nb = 0; nb < 2; nb++) {
                const float* Ab = base + nb * 2304;
                #pragma unroll
                for (int mt = 0; mt < 2; mt++) {
                    int m = wm + mt * 16 + r;
                    a[nb][mt][0] = __float_as_uint(Ab[m * 36 + k0 + tig]);
                    a[nb][mt][1] = __float_as_uint(Ab[(m + 8) * 36 + k0 + tig]);
                    a[nb][mt][2] = __float_as_uint(Ab[m * 36 + k0 + tig + 4]);
                    a[nb][mt][3] = __float_as_uint(Ab[(m + 8) * 36 + k0 + tig + 4]);
                }
            }
            #pragma unroll
            for (int nt = 0; nt < 4; nt++) {
                int nn = wn + nt * 8 + r;
                b[nt][0] = __float_as_uint(base[4608 + nn * 36 + k0 + tig]);
                b[nt][1] = __float_as_uint(base[4608 + nn * 36 + k0 + tig + 4]);
            }
            #pragma unroll
            for (int nb = 0; nb < 2; nb++)
                #pragma unroll
                for (int mt = 0; mt < 2; mt++)
                    #pragma unroll
                    for (int nt = 0; nt < 4; nt++)
                        mma_tf32(acc[nb][mt][nt], a[nb][mt], b[nt]);
        }
    }

    // epilogue: transposed store out[c'][p] for both batches
    #pragma unroll
    for (int nb = 0; nb < 2; nb++) {
        float* ob = out + (size_t)nb * CH * PPIX;
        #pragma unroll
        for (int mt = 0; mt < 2; mt++) {
            int row0 = m0 + wm + mt * 16 + r;
            #pragma unroll
            for (int nt = 0; nt < 4; nt++) {
                int cc = c0 + wn + nt * 8 + 2 * tig;
                float b0 = bout[cc], b1 = bout[cc + 1];
                ob[(size_t)cc * PPIX + row0]           = acc[nb][mt][nt][0] + b0;
                ob[(size_t)(cc + 1) * PPIX + row0]     = acc[nb][mt][nt][1] + b1;
                ob[(size_t)cc * PPIX + row0 + 8]       = acc[nb][mt][nt][2] + b0;
                ob[(size_t)(cc + 1) * PPIX + row0 + 8] = acc[nb][mt][nt][3] + b1;
            }
        }
    }
}

extern "C" void kernel_launch(void* const* d_in, const int* in_sizes, int n_in,
                              void* d_out, int out_size) {
    const float* queries = (const float*)d_in[0];
    const float* key     = (const float*)d_in[1];
    const float* pos     = (const float*)d_in[2];
    const float* ipw     = (const float*)d_in[3];
    const float* ipb     = (const float*)d_in[4];
    const float* opw     = (const float*)d_in[5];
    const float* opb     = (const float*)d_in[6];
    float* out = (float*)d_out;

    const int proj_smem = NSTG * 5 * 2304 * (int)sizeof(float);  // 138240
    const int outp_smem = NSTG * OUT_STG * (int)sizeof(float);   // 82944
    const int attn_smem = HALOSZ * ROWP * (int)sizeof(float);    // 57600

    cudaFuncSetAttribute(proj_gemm,    cudaFuncAttributeMaxDynamicSharedMemorySize, proj_smem);
    cudaFuncSetAttribute(outproj_gemm, cudaFuncAttributeMaxDynamicSharedMemorySize, outp_smem);
    cudaFuncSetAttribute(attn_kernel,  cudaFuncAttributeMaxDynamicSharedMemorySize, attn_smem);

    w_tf32_kernel<<<512, 128>>>(ipw, opw);
    bconst_kernel<<<32, 256>>>(ipw, ipb, pos);
    proj_gemm<<<dim3(49, 4, 2), 128, proj_smem>>>(queries, key, ipb);
    attn_kernel<<<dim3(4, 4, 16), 256, attn_smem>>>();
    outproj_gemm<<<dim3(49, 4, 1), 128, outp_smem>>>(opb, out);
}

// round 8
// speedup vs baseline: 1.0443x; 1.0443x over previous
#include <cuda_runtime.h>
#include <cstdint>

#define PPIX 3136
#define CH 256
#define DIM 32
#define KER 7
#define K2 49
#define TILE 14
#define HALO 20
#define HALOSZ 400
#define ROWP 36

// scratch (allocation-free rule: device globals)
__device__ __align__(16) float g_Qp[2 * PPIX * CH];
__device__ __align__(16) float g_Kp[2 * PPIX * CH];
__device__ __align__(16) float g_Vp[2 * PPIX * CH];
__device__ __align__(16) float g_O [2 * PPIX * CH];
__device__ __align__(16) float g_Wt[4 * CH * CH];     // tf32-rounded Wq,Wk,Wv,Wout
__device__ __align__(16) float g_bck[CH];
__device__ __align__(16) float g_bcv[CH];

// ---------------------------------------------------------------------------
// helpers
// ---------------------------------------------------------------------------
__device__ __forceinline__ uint32_t f2tf(float x) {
    uint32_t r;
    asm("cvt.rna.tf32.f32 %0, %1;" : "=r"(r) : "f"(x));
    return r;
}
__device__ __forceinline__ float f2tf_f(float x) { return __uint_as_float(f2tf(x)); }
__device__ __forceinline__ void mma_tf32(float c[4], const uint32_t a[4], const uint32_t b[2]) {
    asm volatile(
        "mma.sync.aligned.m16n8k8.row.col.f32.tf32.tf32.f32 "
        "{%0,%1,%2,%3}, {%4,%5,%6,%7}, {%8,%9}, {%0,%1,%2,%3};"
        : "+f"(c[0]), "+f"(c[1]), "+f"(c[2]), "+f"(c[3])
        : "r"(a[0]), "r"(a[1]), "r"(a[2]), "r"(a[3]), "r"(b[0]), "r"(b[1]));
}
__device__ __forceinline__ void cp16(float* smem_dst, const float* gmem_src) {
    uint32_t s = (uint32_t)__cvta_generic_to_shared(smem_dst);
    asm volatile("cp.async.cg.shared.global [%0], [%1], 16;" :: "r"(s), "l"(gmem_src));
}
#define CP_COMMIT()  asm volatile("cp.async.commit_group;")
#define CP_WAIT1()   asm volatile("cp.async.wait_group 1;")
#define CP_WAIT0()   asm volatile("cp.async.wait_group 0;")

#define PROJ_STG (5 * 2304)   // A_q[32][72] + A_k[32][72] + 3x B[64][36] (floats)
#define OUT_STG  (3 * 2304)   // A0[64][36] + A1[64][36] + B[64][36]

// ---------------------------------------------------------------------------
// tf32-round all weights into g_Wt:  [0..3*CH*CH) = in_proj, then out_proj
// ---------------------------------------------------------------------------
__global__ void w_tf32_kernel(const float* __restrict__ ipw, const float* __restrict__ opw) {
    int i = blockIdx.x * 128 + threadIdx.x;            // float4 index, 65536 total
    const int IPW4 = 3 * CH * CH / 4;                   // 49152
    float4 v = (i < IPW4) ? reinterpret_cast<const float4*>(ipw)[i]
                          : reinterpret_cast<const float4*>(opw)[i - IPW4];
    v.x = f2tf_f(v.x); v.y = f2tf_f(v.y); v.z = f2tf_f(v.z); v.w = f2tf_f(v.w);
    reinterpret_cast<float4*>(g_Wt)[i] = v;
}

// ---------------------------------------------------------------------------
// bconst[c'] = pos * sum_c W[c'][c] + b[c']   (K and V blocks of in_proj)
// ---------------------------------------------------------------------------
__global__ void bconst_kernel(const float* __restrict__ W, const float* __restrict__ b,
                              const float* __restrict__ pos) {
    int c = blockIdx.x * 8 + (threadIdx.x >> 5);
    int lane = threadIdx.x & 31;
    float p = pos[0];
    const float4* wk = reinterpret_cast<const float4*>(W + (size_t)(CH + c) * CH);
    const float4* wv = reinterpret_cast<const float4*>(W + (size_t)(2 * CH + c) * CH);
    float4 a0 = wk[lane * 2], a1 = wk[lane * 2 + 1];
    float4 v0 = wv[lane * 2], v1 = wv[lane * 2 + 1];
    float sk = a0.x + a0.y + a0.z + a0.w + a1.x + a1.y + a1.z + a1.w;
    float sv = v0.x + v0.y + v0.z + v0.w + v1.x + v1.y + v1.z + v1.w;
    #pragma unroll
    for (int o = 16; o > 0; o >>= 1) {
        sk += __shfl_xor_sync(0xffffffffu, sk, o);
        sv += __shfl_xor_sync(0xffffffffu, sv, o);
    }
    if (lane == 0) {
        g_bck[c] = p * sk + b[CH + c];
        g_bcv[c] = p * sv + b[2 * CH + c];
    }
}

// ---------------------------------------------------------------------------
// Fused Q/K/V projection (tf32, BM=64 BN=64 BK=32, cp.async 2-stage,
// 128 threads, 2 CTAs/SM): A tiles loaded once, 3 accumulators, 24 MMA/kstep.
// Stage: A_q | A_k (k-major [32][72]) | B_q | B_k | B_v (n-major [64][36]).
// Weights are pre-rounded tf32 (no cvt); only A fragments get cvt.
// blockIdx.z = n
// ---------------------------------------------------------------------------
__global__ void __launch_bounds__(128, 2)
proj_gemm(const float* __restrict__ queries, const float* __restrict__ key,
          const float* __restrict__ bvec) {
    int n = blockIdx.z;
    const float* InQ = queries + (size_t)n * CH * PPIX;
    const float* InK = key     + (size_t)n * CH * PPIX;

    extern __shared__ float smf[];     // [2][PROJ_STG]

    int tid = threadIdx.x;
    int m0 = blockIdx.x * 64;
    int c0 = blockIdx.y * 64;
    int w = tid >> 5, lane = tid & 31;
    int r = lane >> 2, tig = lane & 3;
    int wm = (w & 1) * 32;
    int wn = (w >> 1) * 32;

    float acc[3][2][4][4] = {};

    auto issue5 = [&](int t) {
        float* base = smf + (t & 1) * PROJ_STG;
        int kt = t * 32;
        #pragma unroll
        for (int i = 0; i < 4; i++) {
            int id = tid + 128 * i;
            int row = id >> 4;                 // 0..31
            int c4 = (id & 15) * 4;            // 0..60
            cp16(base + row * 72 + c4,        InQ + (size_t)(kt + row) * PPIX + m0 + c4);
            cp16(base + 2304 + row * 72 + c4, InK + (size_t)(kt + row) * PPIX + m0 + c4);
        }
        #pragma unroll
        for (int pr = 0; pr < 3; pr++) {
            const float* W = g_Wt + (size_t)pr * CH * CH;
            float* Bs = base + 2 * 2304 + pr * 2304;
            #pragma unroll
            for (int i = 0; i < 4; i++) {
                int id = tid + 128 * i;
                int row = id >> 3;             // 0..63
                int k4 = (id & 7) * 4;         // 0..28
                cp16(Bs + row * 36 + k4, W + (size_t)(c0 + row) * CH + kt + k4);
            }
        }
        CP_COMMIT();
    };

    issue5(0);

    for (int it = 0; it < 8; it++) {
        if (it + 1 < 8) { issue5(it + 1); CP_WAIT1(); }
        else            { CP_WAIT0(); }
        __syncthreads();                       // stage `it` visible to all

        const float* base = smf + (it & 1) * PROJ_STG;
        #pragma unroll
        for (int ks = 0; ks < 4; ks++) {
            int k0 = ks * 8;
            uint32_t aq[2][4], ak[2][4];
            #pragma unroll
            for (int mt = 0; mt < 2; mt++) {
                int m = wm + mt * 16 + r;
                aq[mt][0] = f2tf(base[(k0 + tig) * 72 + m]);
                aq[mt][1] = f2tf(base[(k0 + tig) * 72 + m + 8]);
                aq[mt][2] = f2tf(base[(k0 + tig + 4) * 72 + m]);
                aq[mt][3] = f2tf(base[(k0 + tig + 4) * 72 + m + 8]);
                ak[mt][0] = f2tf(base[2304 + (k0 + tig) * 72 + m]);
                ak[mt][1] = f2tf(base[2304 + (k0 + tig) * 72 + m + 8]);
                ak[mt][2] = f2tf(base[2304 + (k0 + tig + 4) * 72 + m]);
                ak[mt][3] = f2tf(base[2304 + (k0 + tig + 4) * 72 + m + 8]);
            }
            #pragma unroll
            for (int pr = 0; pr < 3; pr++) {
                const float* Bb = base + 2 * 2304 + pr * 2304;
                uint32_t b[4][2];
                #pragma unroll
                for (int nt = 0; nt < 4; nt++) {
                    int nn = wn + nt * 8 + r;
                    b[nt][0] = __float_as_uint(Bb[nn * 36 + k0 + tig]);
                    b[nt][1] = __float_as_uint(Bb[nn * 36 + k0 + tig + 4]);
                }
                #pragma unroll
                for (int mt = 0; mt < 2; mt++)
                    #pragma unroll
                    for (int nt = 0; nt < 4; nt++)
                        mma_tf32(acc[pr][mt][nt], (pr == 0) ? aq[mt] : ak[mt], b[nt]);
            }
        }
        __syncthreads();                       // all done reading before reissue
    }

    float* Outs[3] = { g_Qp + (size_t)n * PPIX * CH,
                       g_Kp + (size_t)n * PPIX * CH,
                       g_Vp + (size_t)n * PPIX * CH };
    #pragma unroll
    for (int pr = 0; pr < 3; pr++) {
        float* Out = Outs[pr];
        #pragma unroll
        for (int mt = 0; mt < 2; mt++) {
            int row0 = m0 + wm + mt * 16 + r;
            #pragma unroll
            for (int nt = 0; nt < 4; nt++) {
                int cc = c0 + wn + nt * 8 + 2 * tig;
                float b0 = (pr == 0) ? bvec[cc] : 0.f;
                float b1 = (pr == 0) ? bvec[cc + 1] : 0.f;
                *reinterpret_cast<float2*>(Out + (size_t)row0 * CH + cc) =
                    make_float2(acc[pr][mt][nt][0] + b0, acc[pr][mt][nt][1] + b1);
                *reinterpret_cast<float2*>(Out + (size_t)(row0 + 8) * CH + cc) =
                    make_float2(acc[pr][mt][nt][2] + b0, acc[pr][mt][nt][3] + b1);
            }
        }
    }
}

// ---------------------------------------------------------------------------
// Local attention: 1 pixel/thread, 256 threads, phase-split smem, 2 blocks/SM.
// Dot products use 4 independent accumulators (chain depth 8, not 32).
// Output stored tf32-rounded (outproj needs no cvt; numerically identical).
// ---------------------------------------------------------------------------
__global__ void __launch_bounds__(256, 2) attn_kernel() {
    extern __shared__ float smf[];     // HALOSZ * ROWP floats

    int tx0 = blockIdx.x * TILE;
    int ty0 = blockIdx.y * TILE;
    int h = blockIdx.z & 7;
    int n = blockIdx.z >> 3;
    int tid = threadIdx.x;
    int cbase = h * DIM;

    const float* Kp = g_Kp + (size_t)n * PPIX * CH;
    const float* Vp = g_Vp + (size_t)n * PPIX * CH;

    int ly = tid / TILE, lx = tid % TILE;
    bool active = tid < TILE * TILE;
    int p = (ty0 + ly) * 56 + (tx0 + lx);

    float4 q4[8];
    if (active) {
        const float* qptr = g_Qp + (size_t)n * PPIX * CH + (size_t)p * CH + cbase;
        #pragma unroll
        for (int i = 0; i < 8; i++)
            q4[i] = *reinterpret_cast<const float4*>(qptr + i * 4);
    }

    // ---- phase 1: K halo fill ----
    for (int idx = tid; idx < HALOSZ * 8; idx += 256) {
        int hp = idx >> 3;
        int c4 = (idx & 7) * 4;
        int gy = ty0 - 3 + hp / HALO;
        int gx = tx0 - 3 + hp % HALO;
        float4 kv = *reinterpret_cast<const float4*>(g_bck + cbase + c4);
        if (gy >= 0 && gy < 56 && gx >= 0 && gx < 56) {
            float4 k4 = *reinterpret_cast<const float4*>(Kp + (size_t)(gy * 56 + gx) * CH + cbase + c4);
            kv.x += k4.x; kv.y += k4.y; kv.z += k4.z; kv.w += k4.w;
        }
        *reinterpret_cast<float4*>(smf + hp * ROWP + c4) = kv;
    }
    __syncthreads();

    float sc[K2];
    if (active) {
        const float scale = 0.17677669529663687f;   // 1/sqrt(32)
        #pragma unroll
        for (int ti = 0; ti < KER; ti++) {
            #pragma unroll
            for (int tj = 0; tj < KER; tj++) {
                const float4* kr = reinterpret_cast<const float4*>(
                    smf + ((ly + ti) * HALO + (lx + tj)) * ROWP);
                float s0 = 0.f, s1 = 0.f, s2 = 0.f, s3 = 0.f;
                #pragma unroll
                for (int c = 0; c < 8; c++) {
                    float4 k4 = kr[c];
                    s0 += q4[c].x * k4.x;
                    s1 += q4[c].y * k4.y;
                    s2 += q4[c].z * k4.z;
                    s3 += q4[c].w * k4.w;
                }
                sc[ti * KER + tj] = ((s0 + s1) + (s2 + s3)) * scale;
            }
        }
        float mx = sc[0];
        #pragma unroll
        for (int t = 1; t < K2; t++) mx = fmaxf(mx, sc[t]);
        float sum = 0.f;
        #pragma unroll
        for (int t = 0; t < K2; t++) { sc[t] = __expf(sc[t] - mx); sum += sc[t]; }
        float inv = 1.f / sum;
        #pragma unroll
        for (int t = 0; t < K2; t++) sc[t] *= inv;
    }
    __syncthreads();

    // ---- phase 2: V halo fill (same buffer) ----
    for (int idx = tid; idx < HALOSZ * 8; idx += 256) {
        int hp = idx >> 3;
        int c4 = (idx & 7) * 4;
        int gy = ty0 - 3 + hp / HALO;
        int gx = tx0 - 3 + hp % HALO;
        float4 vv = *reinterpret_cast<const float4*>(g_bcv + cbase + c4);
        if (gy >= 0 && gy < 56 && gx >= 0 && gx < 56) {
            float4 v4 = *reinterpret_cast<const float4*>(Vp + (size_t)(gy * 56 + gx) * CH + cbase + c4);
            vv.x += v4.x; vv.y += v4.y; vv.z += v4.z; vv.w += v4.w;
        }
        *reinterpret_cast<float4*>(smf + hp * ROWP + c4) = vv;
    }
    __syncthreads();

    if (active) {
        float4 o4[8];
        #pragma unroll
        for (int c = 0; c < 8; c++) o4[c] = make_float4(0.f, 0.f, 0.f, 0.f);
        #pragma unroll
        for (int ti = 0; ti < KER; ti++) {
            #pragma unroll
            for (int tj = 0; tj < KER; tj++) {
                const float4* vr = reinterpret_cast<const float4*>(
                    smf + ((ly + ti) * HALO + (lx + tj)) * ROWP);
                float wgt = sc[ti * KER + tj];
                #pragma unroll
                for (int c = 0; c < 8; c++) {
                    float4 v4 = vr[c];
                    o4[c].x += wgt * v4.x; o4[c].y += wgt * v4.y;
                    o4[c].z += wgt * v4.z; o4[c].w += wgt * v4.w;
                }
            }
        }
        float* optr = g_O + (size_t)n * PPIX * CH + (size_t)p * CH + cbase;
        #pragma unroll
        for (int i = 0; i < 8; i++) {
            float4 t = o4[i];
            t.x = f2tf_f(t.x); t.y = f2tf_f(t.y); t.z = f2tf_f(t.z); t.w = f2tf_f(t.w);
            *reinterpret_cast<float4*>(optr + i * 4) = t;
        }
    }
}

// ---------------------------------------------------------------------------
// Out projection, both batches fused (tf32, BM=64 BN=64 BK=32, cp.async
// 2-stage, 128 threads, 4 CTAs/SM).  No cvts (inputs already tf32-rounded).
// Stage: A0[64][36] + A1[64][36] + B[64][36].
// ---------------------------------------------------------------------------
__global__ void __launch_bounds__(128, 4)
outproj_gemm(const float* __restrict__ bout, float* __restrict__ out) {
    extern __shared__ float smf[];     // [2][OUT_STG]
    const float* Wout = g_Wt + 3 * CH * CH;

    int tid = threadIdx.x;
    int m0 = blockIdx.x * 64;
    int c0 = blockIdx.y * 64;
    int w = tid >> 5, lane = tid & 31;
    int r = lane >> 2, tig = lane & 3;
    int wm = (w & 1) * 32;
    int wn = (w >> 1) * 32;

    float acc[2][2][4][4] = {};

    auto issue_tile = [&](int t) {
        float* base = smf + (t & 1) * OUT_STG;
        int kt = t * 32;
        #pragma unroll
        for (int i = 0; i < 4; i++) {
            int id = tid + 128 * i;
            int row = id >> 3;                 // 0..63
            int k4 = (id & 7) * 4;
            cp16(base + row * 36 + k4,
                 g_O + (size_t)(m0 + row) * CH + kt + k4);
            cp16(base + 2304 + row * 36 + k4,
                 g_O + (size_t)PPIX * CH + (size_t)(m0 + row) * CH + kt + k4);
            cp16(base + 4608 + row * 36 + k4,
                 Wout + (size_t)(c0 + row) * CH + kt + k4);
        }
        CP_COMMIT();
    };

    issue_tile(0);

    for (int it = 0; it < 8; it++) {
        if (it + 1 < 8) { issue_tile(it + 1); CP_WAIT1(); }
        else            { CP_WAIT0(); }
        __syncthreads();

        const float* base = smf + (it & 1) * OUT_STG;
        #pragma unroll
        for (int ks = 0; ks < 4; ks++) {
            int k0 = ks * 8;
            uint32_t a[2][2][4], b[4][2];
            #pragma unroll
            for (int nb = 0; nb < 2; nb++) {
                const float* Ab = base + nb * 2304;
                #pragma unroll
                for (int mt = 0; mt < 2; mt++) {
                    int m = wm + mt * 16 + r;
                    a[nb][mt][0] = __float_as_uint(Ab[m * 36 + k0 + tig]);
                    a[nb][mt][1] = __float_as_uint(Ab[(m + 8) * 36 + k0 + tig]);
                    a[nb][mt][2] = __float_as_uint(Ab[m * 36 + k0 + tig + 4]);
                    a[nb][mt][3] = __float_as_uint(Ab[(m + 8) * 36 + k0 + tig + 4]);
                }
            }
            #pragma unroll
            for (int nt = 0; nt < 4; nt++) {
                int nn = wn + nt * 8 + r;
                b[nt][0] = __float_as_uint(base[4608 + nn * 36 + k0 + tig]);
                b[nt][1] = __float_as_uint(base[4608 + nn * 36 + k0 + tig + 4]);
            }
            #pragma unroll
            for (int nb = 0; nb < 2; nb++)
                #pragma unroll
                for (int mt = 0; mt < 2; mt++)
                    #pragma unroll
                    for (int nt = 0; nt < 4; nt++)
                        mma_tf32(acc[nb][mt][nt], a[nb][mt], b[nt]);
        }
        __syncthreads();
    }

    // epilogue: transposed store out[c'][p] for both batches
    #pragma unroll
    for (int nb = 0; nb < 2; nb++) {
        float* ob = out + (size_t)nb * CH * PPIX;
        #pragma unroll
        for (int mt = 0; mt < 2; mt++) {
            int row0 = m0 + wm + mt * 16 + r;
            #pragma unroll
            for (int nt = 0; nt < 4; nt++) {
                int cc = c0 + wn + nt * 8 + 2 * tig;
                float b0 = bout[cc], b1 = bout[cc + 1];
                ob[(size_t)cc * PPIX + row0]           = acc[nb][mt][nt][0] + b0;
                ob[(size_t)(cc + 1) * PPIX + row0]     = acc[nb][mt][nt][1] + b1;
                ob[(size_t)cc * PPIX + row0 + 8]       = acc[nb][mt][nt][2] + b0;
                ob[(size_t)(cc + 1) * PPIX + row0 + 8] = acc[nb][mt][nt][3] + b1;
            }
        }
    }
}

extern "C" void kernel_launch(void* const* d_in, const int* in_sizes, int n_in,
                              void* d_out, int out_size) {
    const float* queries = (const float*)d_in[0];
    const float* key     = (const float*)d_in[1];
    const float* pos     = (const float*)d_in[2];
    const float* ipw     = (const float*)d_in[3];
    const float* ipb     = (const float*)d_in[4];
    const float* opw     = (const float*)d_in[5];
    const float* opb     = (const float*)d_in[6];
    float* out = (float*)d_out;

    const int proj_smem = 2 * PROJ_STG * (int)sizeof(float);    // 92160
    const int outp_smem = 2 * OUT_STG * (int)sizeof(float);     // 55296
    const int attn_smem = HALOSZ * ROWP * (int)sizeof(float);   // 57600

    cudaFuncSetAttribute(proj_gemm,    cudaFuncAttributeMaxDynamicSharedMemorySize, proj_smem);
    cudaFuncSetAttribute(outproj_gemm, cudaFuncAttributeMaxDynamicSharedMemorySize, outp_smem);
    cudaFuncSetAttribute(attn_kernel,  cudaFuncAttributeMaxDynamicSharedMemorySize, attn_smem);

    w_tf32_kernel<<<512, 128>>>(ipw, opw);
    bconst_kernel<<<32, 256>>>(ipw, ipb, pos);
    proj_gemm<<<dim3(49, 4, 2), 128, proj_smem>>>(queries, key, ipb);
    attn_kernel<<<dim3(4, 4, 16), 256, attn_smem>>>();
    outproj_gemm<<<dim3(49, 4, 1), 128, outp_smem>>>(opb, out);
}

// round 9
// speedup vs baseline: 1.0984x; 1.0519x over previous
#include <cuda_runtime.h>
#include <cuda_fp16.h>
#include <cstdint>

#define PPIX 3136
#define CH 256
#define DIM 32
#define KER 7
#define K2 49
#define TILE 14
#define HALO 20
#define HALOSZ 400
#define HROW 40     // halfs per halo row (32 ch + pad), 80B, 16B-aligned

// scratch (allocation-free rule: device globals)
__device__ __align__(16) float g_Qp[2 * PPIX * CH];
__device__ __align__(16) float g_Kp[2 * PPIX * CH];
__device__ __align__(16) float g_Vp[2 * PPIX * CH];
__device__ __align__(16) float g_O [2 * PPIX * CH];
__device__ __align__(16) float g_Wt[4 * CH * CH];     // tf32-rounded Wq,Wk,Wv,Wout
__device__ __align__(16) float g_bcv[CH];

// ---------------------------------------------------------------------------
// helpers
// ---------------------------------------------------------------------------
__device__ __forceinline__ uint32_t f2tf(float x) {
    uint32_t r;
    asm("cvt.rna.tf32.f32 %0, %1;" : "=r"(r) : "f"(x));
    return r;
}
__device__ __forceinline__ float f2tf_f(float x) { return __uint_as_float(f2tf(x)); }
__device__ __forceinline__ void mma_tf32(float c[4], const uint32_t a[4], const uint32_t b[2]) {
    asm volatile(
        "mma.sync.aligned.m16n8k8.row.col.f32.tf32.tf32.f32 "
        "{%0,%1,%2,%3}, {%4,%5,%6,%7}, {%8,%9}, {%0,%1,%2,%3};"
        : "+f"(c[0]), "+f"(c[1]), "+f"(c[2]), "+f"(c[3])
        : "r"(a[0]), "r"(a[1]), "r"(a[2]), "r"(a[3]), "r"(b[0]), "r"(b[1]));
}
__device__ __forceinline__ void cp16(float* smem_dst, const float* gmem_src) {
    uint32_t s = (uint32_t)__cvta_generic_to_shared(smem_dst);
    asm volatile("cp.async.cg.shared.global [%0], [%1], 16;" :: "r"(s), "l"(gmem_src));
}
#define CP_COMMIT()  asm volatile("cp.async.commit_group;")
#define CP_WAIT1()   asm volatile("cp.async.wait_group 1;")
#define CP_WAIT0()   asm volatile("cp.async.wait_group 0;")

#define PROJ_STG (5 * 2304)   // A_q[32][72] + A_k[32][72] + 3x B[64][36] (floats)
#define OUT_STG  (3 * 2304)   // A0[64][36] + A1[64][36] + B[64][36]

// ---------------------------------------------------------------------------
// tf32-round all weights into g_Wt:  [0..3*CH*CH) = in_proj, then out_proj
// ---------------------------------------------------------------------------
__global__ void w_tf32_kernel(const float* __restrict__ ipw, const float* __restrict__ opw) {
    int i = blockIdx.x * 128 + threadIdx.x;            // float4 index, 65536 total
    const int IPW4 = 3 * CH * CH / 4;                   // 49152
    float4 v = (i < IPW4) ? reinterpret_cast<const float4*>(ipw)[i]
                          : reinterpret_cast<const float4*>(opw)[i - IPW4];
    v.x = f2tf_f(v.x); v.y = f2tf_f(v.y); v.z = f2tf_f(v.z); v.w = f2tf_f(v.w);
    reinterpret_cast<float4*>(g_Wt)[i] = v;
}

// ---------------------------------------------------------------------------
// bcv[c'] = pos * sum_c Wv[c'][c] + bv[c']   (V block of in_proj only —
// the K-side bias cancels exactly in softmax and is never needed)
// ---------------------------------------------------------------------------
__global__ void bconst_kernel(const float* __restrict__ W, const float* __restrict__ b,
                              const float* __restrict__ pos) {
    int c = blockIdx.x * 8 + (threadIdx.x >> 5);
    int lane = threadIdx.x & 31;
    float p = pos[0];
    const float4* wv = reinterpret_cast<const float4*>(W + (size_t)(2 * CH + c) * CH);
    float4 v0 = wv[lane * 2], v1 = wv[lane * 2 + 1];
    float sv = v0.x + v0.y + v0.z + v0.w + v1.x + v1.y + v1.z + v1.w;
    #pragma unroll
    for (int o = 16; o > 0; o >>= 1)
        sv += __shfl_xor_sync(0xffffffffu, sv, o);
    if (lane == 0)
        g_bcv[c] = p * sv + b[2 * CH + c];
}

// ---------------------------------------------------------------------------
// Fused Q/K/V projection (tf32, BM=64 BN=64 BK=32, cp.async 2-stage,
// 128 threads, 2 CTAs/SM).  blockIdx.z = n
// ---------------------------------------------------------------------------
__global__ void __launch_bounds__(128, 2)
proj_gemm(const float* __restrict__ queries, const float* __restrict__ key,
          const float* __restrict__ bvec) {
    int n = blockIdx.z;
    const float* InQ = queries + (size_t)n * CH * PPIX;
    const float* InK = key     + (size_t)n * CH * PPIX;

    extern __shared__ float smf[];     // [2][PROJ_STG]

    int tid = threadIdx.x;
    int m0 = blockIdx.x * 64;
    int c0 = blockIdx.y * 64;
    int w = tid >> 5, lane = tid & 31;
    int r = lane >> 2, tig = lane & 3;
    int wm = (w & 1) * 32;
    int wn = (w >> 1) * 32;

    float acc[3][2][4][4] = {};

    auto issue5 = [&](int t) {
        float* base = smf + (t & 1) * PROJ_STG;
        int kt = t * 32;
        #pragma unroll
        for (int i = 0; i < 4; i++) {
            int id = tid + 128 * i;
            int row = id >> 4;
            int c4 = (id & 15) * 4;
            cp16(base + row * 72 + c4,        InQ + (size_t)(kt + row) * PPIX + m0 + c4);
            cp16(base + 2304 + row * 72 + c4, InK + (size_t)(kt + row) * PPIX + m0 + c4);
        }
        #pragma unroll
        for (int pr = 0; pr < 3; pr++) {
            const float* W = g_Wt + (size_t)pr * CH * CH;
            float* Bs = base + 2 * 2304 + pr * 2304;
            #pragma unroll
            for (int i = 0; i < 4; i++) {
                int id = tid + 128 * i;
                int row = id >> 3;
                int k4 = (id & 7) * 4;
                cp16(Bs + row * 36 + k4, W + (size_t)(c0 + row) * CH + kt + k4);
            }
        }
        CP_COMMIT();
    };

    issue5(0);

    for (int it = 0; it < 8; it++) {
        if (it + 1 < 8) { issue5(it + 1); CP_WAIT1(); }
        else            { CP_WAIT0(); }
        __syncthreads();

        const float* base = smf + (it & 1) * PROJ_STG;
        #pragma unroll
        for (int ks = 0; ks < 4; ks++) {
            int k0 = ks * 8;
            uint32_t aq[2][4], ak[2][4];
            #pragma unroll
            for (int mt = 0; mt < 2; mt++) {
                int m = wm + mt * 16 + r;
                aq[mt][0] = f2tf(base[(k0 + tig) * 72 + m]);
                aq[mt][1] = f2tf(base[(k0 + tig) * 72 + m + 8]);
                aq[mt][2] = f2tf(base[(k0 + tig + 4) * 72 + m]);
                aq[mt][3] = f2tf(base[(k0 + tig + 4) * 72 + m + 8]);
                ak[mt][0] = f2tf(base[2304 + (k0 + tig) * 72 + m]);
                ak[mt][1] = f2tf(base[2304 + (k0 + tig) * 72 + m + 8]);
                ak[mt][2] = f2tf(base[2304 + (k0 + tig + 4) * 72 + m]);
                ak[mt][3] = f2tf(base[2304 + (k0 + tig + 4) * 72 + m + 8]);
            }
            #pragma unroll
            for (int pr = 0; pr < 3; pr++) {
                const float* Bb = base + 2 * 2304 + pr * 2304;
                uint32_t b[4][2];
                #pragma unroll
                for (int nt = 0; nt < 4; nt++) {
                    int nn = wn + nt * 8 + r;
                    b[nt][0] = __float_as_uint(Bb[nn * 36 + k0 + tig]);
                    b[nt][1] = __float_as_uint(Bb[nn * 36 + k0 + tig + 4]);
                }
                #pragma unroll
                for (int mt = 0; mt < 2; mt++)
                    #pragma unroll
                    for (int nt = 0; nt < 4; nt++)
                        mma_tf32(acc[pr][mt][nt], (pr == 0) ? aq[mt] : ak[mt], b[nt]);
            }
        }
        __syncthreads();
    }

    float* Outs[3] = { g_Qp + (size_t)n * PPIX * CH,
                       g_Kp + (size_t)n * PPIX * CH,
                       g_Vp + (size_t)n * PPIX * CH };
    #pragma unroll
    for (int pr = 0; pr < 3; pr++) {
        float* Out = Outs[pr];
        #pragma unroll
        for (int mt = 0; mt < 2; mt++) {
            int row0 = m0 + wm + mt * 16 + r;
            #pragma unroll
            for (int nt = 0; nt < 4; nt++) {
                int cc = c0 + wn + nt * 8 + 2 * tig;
                float b0 = (pr == 0) ? bvec[cc] : 0.f;
                float b1 = (pr == 0) ? bvec[cc + 1] : 0.f;
                *reinterpret_cast<float2*>(Out + (size_t)row0 * CH + cc) =
                    make_float2(acc[pr][mt][nt][0] + b0, acc[pr][mt][nt][1] + b1);
                *reinterpret_cast<float2*>(Out + (size_t)(row0 + 8) * CH + cc) =
                    make_float2(acc[pr][mt][nt][2] + b0, acc[pr][mt][nt][3] + b1);
            }
        }
    }
}

// ---------------------------------------------------------------------------
// Local attention: K/V halos in fp16 smem (raw Kp/Vp; zeros for padding —
// the scalar pos bias cancels in softmax for K, and adds bcv once for V).
// Both halos resident (64 KB), no phase split, 3 CTAs/SM.
// ---------------------------------------------------------------------------
__global__ void __launch_bounds__(256, 3) attn_kernel() {
    extern __shared__ __half smh[];          // Ks[400*40] | Vs[400*40]
    __half* Ks = smh;
    __half* Vs = smh + HALOSZ * HROW;

    int tx0 = blockIdx.x * TILE;
    int ty0 = blockIdx.y * TILE;
    int h = blockIdx.z & 7;
    int n = blockIdx.z >> 3;
    int tid = threadIdx.x;
    int cbase = h * DIM;

    const float* Kp = g_Kp + (size_t)n * PPIX * CH;
    const float* Vp = g_Vp + (size_t)n * PPIX * CH;

    // fill both halos: idx = (matrix, point, 8-channel chunk)
    for (int idx = tid; idx < HALOSZ * 4 * 2; idx += 256) {
        int m = idx >= HALOSZ * 4;
        int j = m ? idx - HALOSZ * 4 : idx;
        int hp = j >> 2;
        int c8 = (j & 3) * 8;
        int gy = ty0 - 3 + hp / HALO;
        int gx = tx0 - 3 + hp % HALO;
        float4 a = make_float4(0.f, 0.f, 0.f, 0.f);
        float4 b = make_float4(0.f, 0.f, 0.f, 0.f);
        if (gy >= 0 && gy < 56 && gx >= 0 && gx < 56) {
            const float* src = (m ? Vp : Kp) + (size_t)(gy * 56 + gx) * CH + cbase + c8;
            a = *reinterpret_cast<const float4*>(src);
            b = *reinterpret_cast<const float4*>(src + 4);
        }
        __half2 hh[4];
        hh[0] = __floats2half2_rn(a.x, a.y);
        hh[1] = __floats2half2_rn(a.z, a.w);
        hh[2] = __floats2half2_rn(b.x, b.y);
        hh[3] = __floats2half2_rn(b.z, b.w);
        *reinterpret_cast<uint4*>((m ? Vs : Ks) + hp * HROW + c8) =
            *reinterpret_cast<uint4*>(hh);
    }
    __syncthreads();

    if (tid >= TILE * TILE) return;          // no further barriers
    int ly = tid / TILE, lx = tid % TILE;
    int p = (ty0 + ly) * 56 + (tx0 + lx);

    // q scaled by 1/sqrt(d), kept fp32
    const float scale = 0.17677669529663687f;
    float2 q2[16];
    {
        const float* qptr = g_Qp + (size_t)n * PPIX * CH + (size_t)p * CH + cbase;
        #pragma unroll
        for (int i = 0; i < 8; i++) {
            float4 v = *reinterpret_cast<const float4*>(qptr + i * 4);
            q2[2 * i]     = make_float2(v.x * scale, v.y * scale);
            q2[2 * i + 1] = make_float2(v.z * scale, v.w * scale);
        }
    }

    float sc[K2];
    #pragma unroll
    for (int ti = 0; ti < KER; ti++) {
        #pragma unroll
        for (int tj = 0; tj < KER; tj++) {
            const __half* kr = Ks + ((ly + ti) * HALO + (lx + tj)) * HROW;
            __half2 hh[16];
            *reinterpret_cast<uint4*>(hh)      = *reinterpret_cast<const uint4*>(kr);
            *reinterpret_cast<uint4*>(hh + 4)  = *reinterpret_cast<const uint4*>(kr + 8);
            *reinterpret_cast<uint4*>(hh + 8)  = *reinterpret_cast<const uint4*>(kr + 16);
            *reinterpret_cast<uint4*>(hh + 12) = *reinterpret_cast<const uint4*>(kr + 24);
            float s0 = 0.f, s1 = 0.f, s2 = 0.f, s3 = 0.f;
            #pragma unroll
            for (int i = 0; i < 8; i++) {
                float2 f0 = __half22float2(hh[i]);
                float2 f1 = __half22float2(hh[i + 8]);
                s0 += q2[i].x * f0.x;
                s1 += q2[i].y * f0.y;
                s2 += q2[i + 8].x * f1.x;
                s3 += q2[i + 8].y * f1.y;
            }
            sc[ti * KER + tj] = (s0 + s1) + (s2 + s3);
        }
    }

    float mx = sc[0];
    #pragma unroll
    for (int t = 1; t < K2; t++) mx = fmaxf(mx, sc[t]);
    float sum = 0.f;
    #pragma unroll
    for (int t = 0; t < K2; t++) { sc[t] = __expf(sc[t] - mx); sum += sc[t]; }
    float inv = 1.f / sum;
    #pragma unroll
    for (int t = 0; t < K2; t++) sc[t] *= inv;

    float2 o2[16];
    #pragma unroll
    for (int i = 0; i < 16; i++) o2[i] = make_float2(0.f, 0.f);
    #pragma unroll
    for (int ti = 0; ti < KER; ti++) {
        #pragma unroll
        for (int tj = 0; tj < KER; tj++) {
            const __half* vr = Vs + ((ly + ti) * HALO + (lx + tj)) * HROW;
            __half2 hh[16];
            *reinterpret_cast<uint4*>(hh)      = *reinterpret_cast<const uint4*>(vr);
            *reinterpret_cast<uint4*>(hh + 4)  = *reinterpret_cast<const uint4*>(vr + 8);
            *reinterpret_cast<uint4*>(hh + 8)  = *reinterpret_cast<const uint4*>(vr + 16);
            *reinterpret_cast<uint4*>(hh + 12) = *reinterpret_cast<const uint4*>(vr + 24);
            float wgt = sc[ti * KER + tj];
            #pragma unroll
            for (int i = 0; i < 16; i++) {
                float2 f = __half22float2(hh[i]);
                o2[i].x += wgt * f.x;
                o2[i].y += wgt * f.y;
            }
        }
    }

    // add bcv once (sum of weights == 1), tf32-round, store
    float* optr = g_O + (size_t)n * PPIX * CH + (size_t)p * CH + cbase;
    #pragma unroll
    for (int i = 0; i < 8; i++) {
        float4 bc = *reinterpret_cast<const float4*>(g_bcv + cbase + i * 4);
        float4 t;
        t.x = f2tf_f(o2[2 * i].x     + bc.x);
        t.y = f2tf_f(o2[2 * i].y     + bc.y);
        t.z = f2tf_f(o2[2 * i + 1].x + bc.z);
        t.w = f2tf_f(o2[2 * i + 1].y + bc.w);
        *reinterpret_cast<float4*>(optr + i * 4) = t;
    }
}

// ---------------------------------------------------------------------------
// Out projection, both batches fused (tf32, BM=64 BN=64 BK=32, cp.async
// 2-stage, 128 threads, 4 CTAs/SM).  No cvts (inputs already tf32-rounded).
// ---------------------------------------------------------------------------
__global__ void __launch_bounds__(128, 4)
outproj_gemm(const float* __restrict__ bout, float* __restrict__ out) {
    extern __shared__ float smf[];     // [2][OUT_STG]
    const float* Wout = g_Wt + 3 * CH * CH;

    int tid = threadIdx.x;
    int m0 = blockIdx.x * 64;
    int c0 = blockIdx.y * 64;
    int w = tid >> 5, lane = tid & 31;
    int r = lane >> 2, tig = lane & 3;
    int wm = (w & 1) * 32;
    int wn = (w >> 1) * 32;

    float acc[2][2][4][4] = {};

    auto issue_tile = [&](int t) {
        float* base = smf + (t & 1) * OUT_STG;
        int kt = t * 32;
        #pragma unroll
        for (int i = 0; i < 4; i++) {
            int id = tid + 128 * i;
            int row = id >> 3;
            int k4 = (id & 7) * 4;
            cp16(base + row * 36 + k4,
                 g_O + (size_t)(m0 + row) * CH + kt + k4);
            cp16(base + 2304 + row * 36 + k4,
                 g_O + (size_t)PPIX * CH + (size_t)(m0 + row) * CH + kt + k4);
            cp16(base + 4608 + row * 36 + k4,
                 Wout + (size_t)(c0 + row) * CH + kt + k4);
        }
        CP_COMMIT();
    };

    issue_tile(0);

    for (int it = 0; it < 8; it++) {
        if (it + 1 < 8) { issue_tile(it + 1); CP_WAIT1(); }
        else            { CP_WAIT0(); }
        __syncthreads();

        const float* base = smf + (it & 1) * OUT_STG;
        #pragma unroll
        for (int ks = 0; ks < 4; ks++) {
            int k0 = ks * 8;
            uint32_t a[2][2][4], b[4][2];
            #pragma unroll
            for (int nb = 0; nb < 2; nb++) {
                const float* Ab = base + nb * 2304;
                #pragma unroll
                for (int mt = 0; mt < 2; mt++) {
                    int m = wm + mt * 16 + r;
                    a[nb][mt][0] = __float_as_uint(Ab[m * 36 + k0 + tig]);
                    a[nb][mt][1] = __float_as_uint(Ab[(m + 8) * 36 + k0 + tig]);
                    a[nb][mt][2] = __float_as_uint(Ab[m * 36 + k0 + tig + 4]);
                    a[nb][mt][3] = __float_as_uint(Ab[(m + 8) * 36 + k0 + tig + 4]);
                }
            }
            #pragma unroll
            for (int nt = 0; nt < 4; nt++) {
                int nn = wn + nt * 8 + r;
                b[nt][0] = __float_as_uint(base[4608 + nn * 36 + k0 + tig]);
                b[nt][1] = __float_as_uint(base[4608 + nn * 36 + k0 + tig + 4]);
            }
            #pragma unroll
            for (int nb = 0; nb < 2; nb++)
                #pragma unroll
                for (int mt = 0; mt < 2; mt++)
                    #pragma unroll
                    for (int nt = 0; nt < 4; nt++)
                        mma_tf32(acc[nb][mt][nt], a[nb][mt], b[nt]);
        }
        __syncthreads();
    }

    #pragma unroll
    for (int nb = 0; nb < 2; nb++) {
        float* ob = out + (size_t)nb * CH * PPIX;
        #pragma unroll
        for (int mt = 0; mt < 2; mt++) {
            int row0 = m0 + wm + mt * 16 + r;
            #pragma unroll
            for (int nt = 0; nt < 4; nt++) {
                int cc = c0 + wn + nt * 8 + 2 * tig;
                float b0 = bout[cc], b1 = bout[cc + 1];
                ob[(size_t)cc * PPIX + row0]           = acc[nb][mt][nt][0] + b0;
                ob[(size_t)(cc + 1) * PPIX + row0]     = acc[nb][mt][nt][1] + b1;
                ob[(size_t)cc * PPIX + row0 + 8]       = acc[nb][mt][nt][2] + b0;
                ob[(size_t)(cc + 1) * PPIX + row0 + 8] = acc[nb][mt][nt][3] + b1;
            }
        }
    }
}

extern "C" void kernel_launch(void* const* d_in, const int* in_sizes, int n_in,
                              void* d_out, int out_size) {
    const float* queries = (const float*)d_in[0];
    const float* key     = (const float*)d_in[1];
    const float* pos     = (const float*)d_in[2];
    const float* ipw     = (const float*)d_in[3];
    const float* ipb     = (const float*)d_in[4];
    const float* opw     = (const float*)d_in[5];
    const float* opb     = (const float*)d_in[6];
    float* out = (float*)d_out;

    const int proj_smem = 2 * PROJ_STG * (int)sizeof(float);        // 92160
    const int outp_smem = 2 * OUT_STG * (int)sizeof(float);         // 55296
    const int attn_smem = 2 * HALOSZ * HROW * (int)sizeof(__half);  // 64000

    cudaFuncSetAttribute(proj_gemm,    cudaFuncAttributeMaxDynamicSharedMemorySize, proj_smem);
    cudaFuncSetAttribute(outproj_gemm, cudaFuncAttributeMaxDynamicSharedMemorySize, outp_smem);
    cudaFuncSetAttribute(attn_kernel,  cudaFuncAttributeMaxDynamicSharedMemorySize, attn_smem);

    w_tf32_kernel<<<512, 128>>>(ipw, opw);
    bconst_kernel<<<32, 256>>>(ipw, ipb, pos);
    proj_gemm<<<dim3(49, 4, 2), 128, proj_smem>>>(queries, key, ipb);
    attn_kernel<<<dim3(4, 4, 16), 256, attn_smem>>>();
    outproj_gemm<<<dim3(49, 4, 1), 128, outp_smem>>>(opb, out);
}

// round 10
// speedup vs baseline: 1.1561x; 1.0525x over previous
#include <cuda_runtime.h>
#include <cuda_fp16.h>
#include <cstdint>

#define PPIX 3136
#define CH 256
#define DIM 32
#define KER 7
#define K2 49
#define TILE 14
#define HALO 20
#define HALOSZ 400
#define HROW 40     // halfs per halo row (32 ch + pad), 80B, 16B-aligned
#define SROW 50     // floats per score row (49 + pad)

// scratch (allocation-free rule: device globals)
__device__ __align__(16) float g_Qp[2 * PPIX * CH];
__device__ __align__(16) float g_Kp[2 * PPIX * CH];
__device__ __align__(16) float g_Vp[2 * PPIX * CH];
__device__ __align__(16) float g_O [2 * PPIX * CH];
__device__ __align__(16) float g_Wt[4 * CH * CH];     // tf32-rounded Wq,Wk,Wv,Wout
__device__ __align__(16) float g_bcv[CH];

// ---------------------------------------------------------------------------
// helpers
// ---------------------------------------------------------------------------
__device__ __forceinline__ uint32_t f2tf(float x) {
    uint32_t r;
    asm("cvt.rna.tf32.f32 %0, %1;" : "=r"(r) : "f"(x));
    return r;
}
__device__ __forceinline__ float f2tf_f(float x) { return __uint_as_float(f2tf(x)); }
__device__ __forceinline__ void mma_tf32(float c[4], const uint32_t a[4], const uint32_t b[2]) {
    asm volatile(
        "mma.sync.aligned.m16n8k8.row.col.f32.tf32.tf32.f32 "
        "{%0,%1,%2,%3}, {%4,%5,%6,%7}, {%8,%9}, {%0,%1,%2,%3};"
        : "+f"(c[0]), "+f"(c[1]), "+f"(c[2]), "+f"(c[3])
        : "r"(a[0]), "r"(a[1]), "r"(a[2]), "r"(a[3]), "r"(b[0]), "r"(b[1]));
}
__device__ __forceinline__ void cp16(float* smem_dst, const float* gmem_src) {
    uint32_t s = (uint32_t)__cvta_generic_to_shared(smem_dst);
    asm volatile("cp.async.cg.shared.global [%0], [%1], 16;" :: "r"(s), "l"(gmem_src));
}
#define CP_COMMIT()  asm volatile("cp.async.commit_group;")
#define CP_WAIT1()   asm volatile("cp.async.wait_group 1;")
#define CP_WAIT0()   asm volatile("cp.async.wait_group 0;")

#define PROJ_STG (5 * 2304)   // A_q[32][72] + A_k[32][72] + 3x B[64][36] (floats)
#define OUT_STG  (3 * 2304)   // A0[64][36] + A1[64][36] + B[64][36]

// ---------------------------------------------------------------------------
// tf32-round all weights into g_Wt:  [0..3*CH*CH) = in_proj, then out_proj
// ---------------------------------------------------------------------------
__global__ void w_tf32_kernel(const float* __restrict__ ipw, const float* __restrict__ opw) {
    int i = blockIdx.x * 128 + threadIdx.x;            // float4 index, 65536 total
    const int IPW4 = 3 * CH * CH / 4;                   // 49152
    float4 v = (i < IPW4) ? reinterpret_cast<const float4*>(ipw)[i]
                          : reinterpret_cast<const float4*>(opw)[i - IPW4];
    v.x = f2tf_f(v.x); v.y = f2tf_f(v.y); v.z = f2tf_f(v.z); v.w = f2tf_f(v.w);
    reinterpret_cast<float4*>(g_Wt)[i] = v;
}

// ---------------------------------------------------------------------------
// bcv[c'] = pos * sum_c Wv[c'][c] + bv[c']   (V block only; K-side bias
// cancels exactly in softmax)
// ---------------------------------------------------------------------------
__global__ void bconst_kernel(const float* __restrict__ W, const float* __restrict__ b,
                              const float* __restrict__ pos) {
    int c = blockIdx.x * 8 + (threadIdx.x >> 5);
    int lane = threadIdx.x & 31;
    float p = pos[0];
    const float4* wv = reinterpret_cast<const float4*>(W + (size_t)(2 * CH + c) * CH);
    float4 v0 = wv[lane * 2], v1 = wv[lane * 2 + 1];
    float sv = v0.x + v0.y + v0.z + v0.w + v1.x + v1.y + v1.z + v1.w;
    #pragma unroll
    for (int o = 16; o > 0; o >>= 1)
        sv += __shfl_xor_sync(0xffffffffu, sv, o);
    if (lane == 0)
        g_bcv[c] = p * sv + b[2 * CH + c];
}

// ---------------------------------------------------------------------------
// Fused Q/K/V projection (tf32, BM=64 BN=64 BK=32, cp.async 2-stage,
// 128 threads, 2 CTAs/SM).  blockIdx.z = n
// ---------------------------------------------------------------------------
__global__ void __launch_bounds__(128, 2)
proj_gemm(const float* __restrict__ queries, const float* __restrict__ key,
          const float* __restrict__ bvec) {
    int n = blockIdx.z;
    const float* InQ = queries + (size_t)n * CH * PPIX;
    const float* InK = key     + (size_t)n * CH * PPIX;

    extern __shared__ float smf[];     // [2][PROJ_STG]

    int tid = threadIdx.x;
    int m0 = blockIdx.x * 64;
    int c0 = blockIdx.y * 64;
    int w = tid >> 5, lane = tid & 31;
    int r = lane >> 2, tig = lane & 3;
    int wm = (w & 1) * 32;
    int wn = (w >> 1) * 32;

    float acc[3][2][4][4] = {};

    auto issue5 = [&](int t) {
        float* base = smf + (t & 1) * PROJ_STG;
        int kt = t * 32;
        #pragma unroll
        for (int i = 0; i < 4; i++) {
            int id = tid + 128 * i;
            int row = id >> 4;
            int c4 = (id & 15) * 4;
            cp16(base + row * 72 + c4,        InQ + (size_t)(kt + row) * PPIX + m0 + c4);
            cp16(base + 2304 + row * 72 + c4, InK + (size_t)(kt + row) * PPIX + m0 + c4);
        }
        #pragma unroll
        for (int pr = 0; pr < 3; pr++) {
            const float* W = g_Wt + (size_t)pr * CH * CH;
            float* Bs = base + 2 * 2304 + pr * 2304;
            #pragma unroll
            for (int i = 0; i < 4; i++) {
                int id = tid + 128 * i;
                int row = id >> 3;
                int k4 = (id & 7) * 4;
                cp16(Bs + row * 36 + k4, W + (size_t)(c0 + row) * CH + kt + k4);
            }
        }
        CP_COMMIT();
    };

    issue5(0);

    for (int it = 0; it < 8; it++) {
        if (it + 1 < 8) { issue5(it + 1); CP_WAIT1(); }
        else            { CP_WAIT0(); }
        __syncthreads();

        const float* base = smf + (it & 1) * PROJ_STG;
        #pragma unroll
        for (int ks = 0; ks < 4; ks++) {
            int k0 = ks * 8;
            uint32_t aq[2][4], ak[2][4];
            #pragma unroll
            for (int mt = 0; mt < 2; mt++) {
                int m = wm + mt * 16 + r;
                aq[mt][0] = f2tf(base[(k0 + tig) * 72 + m]);
                aq[mt][1] = f2tf(base[(k0 + tig) * 72 + m + 8]);
                aq[mt][2] = f2tf(base[(k0 + tig + 4) * 72 + m]);
                aq[mt][3] = f2tf(base[(k0 + tig + 4) * 72 + m + 8]);
                ak[mt][0] = f2tf(base[2304 + (k0 + tig) * 72 + m]);
                ak[mt][1] = f2tf(base[2304 + (k0 + tig) * 72 + m + 8]);
                ak[mt][2] = f2tf(base[2304 + (k0 + tig + 4) * 72 + m]);
                ak[mt][3] = f2tf(base[2304 + (k0 + tig + 4) * 72 + m + 8]);
            }
            #pragma unroll
            for (int pr = 0; pr < 3; pr++) {
                const float* Bb = base + 2 * 2304 + pr * 2304;
                uint32_t b[4][2];
                #pragma unroll
                for (int nt = 0; nt < 4; nt++) {
                    int nn = wn + nt * 8 + r;
                    b[nt][0] = __float_as_uint(Bb[nn * 36 + k0 + tig]);
                    b[nt][1] = __float_as_uint(Bb[nn * 36 + k0 + tig + 4]);
                }
                #pragma unroll
                for (int mt = 0; mt < 2; mt++)
                    #pragma unroll
                    for (int nt = 0; nt < 4; nt++)
                        mma_tf32(acc[pr][mt][nt], (pr == 0) ? aq[mt] : ak[mt], b[nt]);
            }
        }
        __syncthreads();
    }

    float* Outs[3] = { g_Qp + (size_t)n * PPIX * CH,
                       g_Kp + (size_t)n * PPIX * CH,
                       g_Vp + (size_t)n * PPIX * CH };
    #pragma unroll
    for (int pr = 0; pr < 3; pr++) {
        float* Out = Outs[pr];
        #pragma unroll
        for (int mt = 0; mt < 2; mt++) {
            int row0 = m0 + wm + mt * 16 + r;
            #pragma unroll
            for (int nt = 0; nt < 4; nt++) {
                int cc = c0 + wn + nt * 8 + 2 * tig;
                float b0 = (pr == 0) ? bvec[cc] : 0.f;
                float b1 = (pr == 0) ? bvec[cc + 1] : 0.f;
                *reinterpret_cast<float2*>(Out + (size_t)row0 * CH + cc) =
                    make_float2(acc[pr][mt][nt][0] + b0, acc[pr][mt][nt][1] + b1);
                *reinterpret_cast<float2*>(Out + (size_t)(row0 + 8) * CH + cc) =
                    make_float2(acc[pr][mt][nt][2] + b0, acc[pr][mt][nt][3] + b1);
            }
        }
    }
}

// ---------------------------------------------------------------------------
// Local attention v3: thread PAIR per pixel (16 channels each), 512 threads,
// fp16 K/V halos + f32 score rows in smem, 2 CTAs/SM (~28 warps/SM).
// Scores: own-half dot + shfl_xor(1); softmax weights staged in smem.
// ---------------------------------------------------------------------------
__global__ void __launch_bounds__(512, 2) attn_kernel() {
    extern __shared__ char smraw[];
    __half* Ks = reinterpret_cast<__half*>(smraw);
    __half* Vs = Ks + HALOSZ * HROW;
    float*  Ssc = reinterpret_cast<float*>(smraw + 2 * HALOSZ * HROW * sizeof(__half));

    int tx0 = blockIdx.x * TILE;
    int ty0 = blockIdx.y * TILE;
    int h = blockIdx.z & 7;
    int n = blockIdx.z >> 3;
    int tid = threadIdx.x;
    int cbase = h * DIM;

    const float* Kp = g_Kp + (size_t)n * PPIX * CH;
    const float* Vp = g_Vp + (size_t)n * PPIX * CH;

    // fill both halos (raw Kp/Vp; zeros for padding — pos bias handled exactly
    // via softmax cancellation + single bcv add)
    for (int idx = tid; idx < HALOSZ * 4 * 2; idx += 512) {
        int m = idx >= HALOSZ * 4;
        int j = m ? idx - HALOSZ * 4 : idx;
        int hp = j >> 2;
        int c8 = (j & 3) * 8;
        int gy = ty0 - 3 + hp / HALO;
        int gx = tx0 - 3 + hp % HALO;
        float4 a = make_float4(0.f, 0.f, 0.f, 0.f);
        float4 b = make_float4(0.f, 0.f, 0.f, 0.f);
        if (gy >= 0 && gy < 56 && gx >= 0 && gx < 56) {
            const float* src = (m ? Vp : Kp) + (size_t)(gy * 56 + gx) * CH + cbase + c8;
            a = *reinterpret_cast<const float4*>(src);
            b = *reinterpret_cast<const float4*>(src + 4);
        }
        __half2 hh[4];
        hh[0] = __floats2half2_rn(a.x, a.y);
        hh[1] = __floats2half2_rn(a.z, a.w);
        hh[2] = __floats2half2_rn(b.x, b.y);
        hh[3] = __floats2half2_rn(b.z, b.w);
        *reinterpret_cast<uint4*>((m ? Vs : Ks) + hp * HROW + c8) =
            *reinterpret_cast<uint4*>(hh);
    }
    __syncthreads();

    if (tid >= 2 * TILE * TILE) return;      // no block barriers after this
    int pix = tid >> 1;
    int half = tid & 1;
    unsigned msk = (tid < 384) ? 0xffffffffu : 0xffu;   // warp 12 partially active
    int ly = pix / TILE, lx = pix % TILE;
    int p = (ty0 + ly) * 56 + (tx0 + lx);
    int coff = half * 16;                    // this thread's 16 channels
    float* srow = Ssc + pix * SROW;

    // q (16 channels), pre-scaled
    const float scale = 0.17677669529663687f;
    float2 q2[8];
    {
        const float* qptr = g_Qp + (size_t)n * PPIX * CH + (size_t)p * CH + cbase + coff;
        #pragma unroll
        for (int i = 0; i < 4; i++) {
            float4 v = *reinterpret_cast<const float4*>(qptr + i * 4);
            q2[2 * i]     = make_float2(v.x * scale, v.y * scale);
            q2[2 * i + 1] = make_float2(v.z * scale, v.w * scale);
        }
    }

    // pass 1: scores -> smem, track max
    float mx = -1e30f;
    #pragma unroll
    for (int ti = 0; ti < KER; ti++) {
        #pragma unroll
        for (int tj = 0; tj < KER; tj++) {
            const __half* kr = Ks + ((ly + ti) * HALO + (lx + tj)) * HROW + coff;
            __half2 hh[8];
            *reinterpret_cast<uint4*>(hh)     = *reinterpret_cast<const uint4*>(kr);
            *reinterpret_cast<uint4*>(hh + 4) = *reinterpret_cast<const uint4*>(kr + 8);
            float s0 = 0.f, s1 = 0.f;
            #pragma unroll
            for (int i = 0; i < 8; i++) {
                float2 f = __half22float2(hh[i]);
                s0 += q2[i].x * f.x;
                s1 += q2[i].y * f.y;
            }
            float s = s0 + s1;
            s += __shfl_xor_sync(msk, s, 1);
            if (half == 0) srow[ti * KER + tj] = s;
            mx = fmaxf(mx, s);
        }
    }
    __syncwarp(msk);

    // pass 2: exp weights -> smem, accumulate sum
    float sum = 0.f;
    #pragma unroll
    for (int t = 0; t < K2; t++) {
        float wgt = __expf(srow[t] - mx);
        sum += wgt;
        if (half == 0) srow[t] = wgt;
    }
    __syncwarp(msk);
    float inv = 1.f / sum;

    // pass 3: o = (sum_t w_t * V_t) * inv   (16 channels)
    float2 o2[8];
    #pragma unroll
    for (int i = 0; i < 8; i++) o2[i] = make_float2(0.f, 0.f);
    #pragma unroll
    for (int ti = 0; ti < KER; ti++) {
        #pragma unroll
        for (int tj = 0; tj < KER; tj++) {
            const __half* vr = Vs + ((ly + ti) * HALO + (lx + tj)) * HROW + coff;
            __half2 hh[8];
            *reinterpret_cast<uint4*>(hh)     = *reinterpret_cast<const uint4*>(vr);
            *reinterpret_cast<uint4*>(hh + 4) = *reinterpret_cast<const uint4*>(vr + 8);
            float wgt = srow[ti * KER + tj];
            #pragma unroll
            for (int i = 0; i < 8; i++) {
                float2 f = __half22float2(hh[i]);
                o2[i].x += wgt * f.x;
                o2[i].y += wgt * f.y;
            }
        }
    }

    // normalize, add bcv once (weights sum to 1), tf32-round, store
    float* optr = g_O + (size_t)n * PPIX * CH + (size_t)p * CH + cbase + coff;
    #pragma unroll
    for (int i = 0; i < 4; i++) {
        float4 bc = *reinterpret_cast<const float4*>(g_bcv + cbase + coff + i * 4);
        float4 t;
        t.x = f2tf_f(o2[2 * i].x     * inv + bc.x);
        t.y = f2tf_f(o2[2 * i].y     * inv + bc.y);
        t.z = f2tf_f(o2[2 * i + 1].x * inv + bc.z);
        t.w = f2tf_f(o2[2 * i + 1].y * inv + bc.w);
        *reinterpret_cast<float4*>(optr + i * 4) = t;
    }
}

// ---------------------------------------------------------------------------
// Out projection, both batches fused (tf32, BM=64 BN=64 BK=32, cp.async
// 2-stage, 128 threads, 4 CTAs/SM).  No cvts (inputs already tf32-rounded).
// ---------------------------------------------------------------------------
__global__ void __launch_bounds__(128, 4)
outproj_gemm(const float* __restrict__ bout, float* __restrict__ out) {
    extern __shared__ float smf[];     // [2][OUT_STG]
    const float* Wout = g_Wt + 3 * CH * CH;

    int tid = threadIdx.x;
    int m0 = blockIdx.x * 64;
    int c0 = blockIdx.y * 64;
    int w = tid >> 5, lane = tid & 31;
    int r = lane >> 2, tig = lane & 3;
    int wm = (w & 1) * 32;
    int wn = (w >> 1) * 32;

    float acc[2][2][4][4] = {};

    auto issue_tile = [&](int t) {
        float* base = smf + (t & 1) * OUT_STG;
        int kt = t * 32;
        #pragma unroll
        for (int i = 0; i < 4; i++) {
            int id = tid + 128 * i;
            int row = id >> 3;
            int k4 = (id & 7) * 4;
            cp16(base + row * 36 + k4,
                 g_O + (size_t)(m0 + row) * CH + kt + k4);
            cp16(base + 2304 + row * 36 + k4,
                 g_O + (size_t)PPIX * CH + (size_t)(m0 + row) * CH + kt + k4);
            cp16(base + 4608 + row * 36 + k4,
                 Wout + (size_t)(c0 + row) * CH + kt + k4);
        }
        CP_COMMIT();
    };

    issue_tile(0);

    for (int it = 0; it < 8; it++) {
        if (it + 1 < 8) { issue_tile(it + 1); CP_WAIT1(); }
        else            { CP_WAIT0(); }
        __syncthreads();

        const float* base = smf + (it & 1) * OUT_STG;
        #pragma unroll
        for (int ks = 0; ks < 4; ks++) {
            int k0 = ks * 8;
            uint32_t a[2][2][4], b[4][2];
            #pragma unroll
            for (int nb = 0; nb < 2; nb++) {
                const float* Ab = base + nb * 2304;
                #pragma unroll
                for (int mt = 0; mt < 2; mt++) {
                    int m = wm + mt * 16 + r;
                    a[nb][mt][0] = __float_as_uint(Ab[m * 36 + k0 + tig]);
                    a[nb][mt][1] = __float_as_uint(Ab[(m + 8) * 36 + k0 + tig]);
                    a[nb][mt][2] = __float_as_uint(Ab[m * 36 + k0 + tig + 4]);
                    a[nb][mt][3] = __float_as_uint(Ab[(m + 8) * 36 + k0 + tig + 4]);
                }
            }
            #pragma unroll
            for (int nt = 0; nt < 4; nt++) {
                int nn = wn + nt * 8 + r;
                b[nt][0] = __float_as_uint(base[4608 + nn * 36 + k0 + tig]);
                b[nt][1] = __float_as_uint(base[4608 + nn * 36 + k0 + tig + 4]);
            }
            #pragma unroll
            for (int nb = 0; nb < 2; nb++)
                #pragma unroll
                for (int mt = 0; mt < 2; mt++)
                    #pragma unroll
                    for (int nt = 0; nt < 4; nt++)
                        mma_tf32(acc[nb][mt][nt], a[nb][mt], b[nt]);
        }
        __syncthreads();
    }

    #pragma unroll
    for (int nb = 0; nb < 2; nb++) {
        float* ob = out + (size_t)nb * CH * PPIX;
        #pragma unroll
        for (int mt = 0; mt < 2; mt++) {
            int row0 = m0 + wm + mt * 16 + r;
            #pragma unroll
            for (int nt = 0; nt < 4; nt++) {
                int cc = c0 + wn + nt * 8 + 2 * tig;
                float b0 = bout[cc], b1 = bout[cc + 1];
                ob[(size_t)cc * PPIX + row0]           = acc[nb][mt][nt][0] + b0;
                ob[(size_t)(cc + 1) * PPIX + row0]     = acc[nb][mt][nt][1] + b1;
                ob[(size_t)cc * PPIX + row0 + 8]       = acc[nb][mt][nt][2] + b0;
                ob[(size_t)(cc + 1) * PPIX + row0 + 8] = acc[nb][mt][nt][3] + b1;
            }
        }
    }
}

extern "C" void kernel_launch(void* const* d_in, const int* in_sizes, int n_in,
                              void* d_out, int out_size) {
    const float* queries = (const float*)d_in[0];
    const float* key     = (const float*)d_in[1];
    const float* pos     = (const float*)d_in[2];
    const float* ipw     = (const float*)d_in[3];
    const float* ipb     = (const float*)d_in[4];
    const float* opw     = (const float*)d_in[5];
    const float* opb     = (const float*)d_in[6];
    float* out = (float*)d_out;

    const int proj_smem = 2 * PROJ_STG * (int)sizeof(float);        // 92160
    const int outp_smem = 2 * OUT_STG * (int)sizeof(float);         // 55296
    const int attn_smem = 2 * HALOSZ * HROW * (int)sizeof(__half)
                        + TILE * TILE * SROW * (int)sizeof(float);  // 64000+39200=103200

    cudaFuncSetAttribute(proj_gemm,    cudaFuncAttributeMaxDynamicSharedMemorySize, proj_smem);
    cudaFuncSetAttribute(outproj_gemm, cudaFuncAttributeMaxDynamicSharedMemorySize, outp_smem);
    cudaFuncSetAttribute(attn_kernel,  cudaFuncAttributeMaxDynamicSharedMemorySize, attn_smem);

    w_tf32_kernel<<<512, 128>>>(ipw, opw);
    bconst_kernel<<<32, 256>>>(ipw, ipb, pos);
    proj_gemm<<<dim3(49, 4, 2), 128, proj_smem>>>(queries, key, ipb);
    attn_kernel<<<dim3(4, 4, 16), 512, attn_smem>>>();
    outproj_gemm<<<dim3(49, 4, 1), 128, outp_smem>>>(opb, out);
}